// round 7
// baseline (speedup 1.0000x reference)
#include <cuda_runtime.h>
#include <cuda_fp16.h>
#include <cstdint>

#define N_USERS 100000
#define N_ITEMS 50000
#define N_NODES (N_USERS + N_ITEMS)
#define EMB 64
#define BATCH 4096
#define MAXDEG 128

// ---- static scratch (no allocations allowed) ----
__device__ __half g_q0[(size_t)N_NODES * EMB];        // 19.2 MB  dinv*emb
__device__ __half g_q1[(size_t)N_NODES * EMB];        // 19.2 MB
__device__ __half g_q2[(size_t)N_NODES * EMB];        // 19.2 MB
__device__ int    g_deg   [N_NODES];
__device__ float  g_dinv  [N_NODES];
__device__ int    g_cursor[N_NODES];                  // zero-init; reset by k_dq each replay
__device__ int    g_col   [(size_t)N_NODES * MAXDEG]; // 76.8 MB padded CSR

// ---------------------------------------------------------------------------
// Direct padded-CSR fill: one atomic per directed edge, slot = row-local index.
// Processes 2 interactions per thread for atomic-latency ILP.
__global__ void k_fill(const int* __restrict__ eu, const int* __restrict__ ei,
                       int* __restrict__ cursor, int* __restrict__ col, int E) {
    int i0 = (blockIdx.x * blockDim.x + threadIdx.x) * 2;
    #pragma unroll
    for (int k = 0; k < 2; ++k) {
        int i = i0 + k;
        if (i < E) {
            int u  = eu[i];
            int it = ei[i] + N_USERS;
            int s1 = atomicAdd(&cursor[u],  1);
            int s2 = atomicAdd(&cursor[it], 1);
            if (s1 < MAXDEG) col[(size_t)u  * MAXDEG + s1] = it;
            if (s2 < MAXDEG) col[(size_t)it * MAXDEG + s2] = u;
        }
    }
}

// ---------------------------------------------------------------------------
// Warp-per-node: deg/dinv from cursor (then reset cursor for next replay),
// and q0 = dinv*emb in fp16 with coalesced lane-parallel loads.
__global__ void k_dq(int* __restrict__ cursor, int* __restrict__ deg,
                     float* __restrict__ dinv,
                     const float4* __restrict__ emb, uint2* __restrict__ q0) {
    int tid = blockIdx.x * blockDim.x + threadIdx.x;
    int n = tid >> 5;
    if (n >= N_NODES) return;
    int lane = tid & 31;

    float d;
    if (lane == 0) {
        int c = cursor[n];
        cursor[n] = 0;                      // ready for next graph replay
        int dg = (c < MAXDEG) ? c : MAXDEG;
        deg[n] = dg;
        d = (dg > 0) ? rsqrtf((float)dg) : 1.0f;
        dinv[n] = d;
    }
    d = __shfl_sync(0xFFFFFFFFu, d, 0);

    if (lane < 16) {
        float4 x = emb[(size_t)n * (EMB / 4) + lane];
        __half2 a = __floats2half2_rn(x.x * d, x.y * d);
        __half2 b = __floats2half2_rn(x.z * d, x.w * d);
        uint2 o;
        o.x = *(unsigned*)&a;
        o.y = *(unsigned*)&b;
        q0[(size_t)n * (EMB / 4) + lane] = o;
    }
}

// ---------------------------------------------------------------------------
// Warp-cooperative fp16 row gather-sum over padded CSR row.
// Quarter-warp per edge slot; lane = 8*quarter + sub; lane loads uint4 (8
// halfs) for columns sub*8..sub*8+7. 16 edges per iteration.
// On return every lane holds the full-row sum for its 8 columns.
__device__ __forceinline__ void row_sum_h(const __half* __restrict__ qin,
                                          const int* __restrict__ colrow,
                                          int dg, int lane, float acc[8]) {
    int quarter = lane >> 3;
    int sub = lane & 7;
    #pragma unroll
    for (int k = 0; k < 8; ++k) acc[k] = 0.0f;

    for (int e0 = 0; e0 < dg; e0 += 16) {
        int base = e0 + 4 * quarter;
        int4 c4 = *(const int4*)(colrow + base);   // row base is 512B-aligned
        int cs[4] = {c4.x, c4.y, c4.z, c4.w};
        #pragma unroll
        for (int j = 0; j < 4; ++j) {
            if (base + j < dg) {
                uint4 qv = *((const uint4*)(qin + (size_t)cs[j] * EMB) + sub);
                const __half2* hp = (const __half2*)&qv;
                float2 f0 = __half22float2(hp[0]);
                float2 f1 = __half22float2(hp[1]);
                float2 f2 = __half22float2(hp[2]);
                float2 f3 = __half22float2(hp[3]);
                acc[0] += f0.x; acc[1] += f0.y;
                acc[2] += f1.x; acc[3] += f1.y;
                acc[4] += f2.x; acc[5] += f2.y;
                acc[6] += f3.x; acc[7] += f3.y;
            }
        }
    }
    #pragma unroll
    for (int k = 0; k < 8; ++k) {
        acc[k] += __shfl_xor_sync(0xFFFFFFFFu, acc[k], 8);
        acc[k] += __shfl_xor_sync(0xFFFFFFFFu, acc[k], 16);
    }
}

// Pull layer: qout[n] = dinv[n]^2 * sum_{s in N(n)} qin[s]
__global__ void __launch_bounds__(256)
k_pull_h(const __half* __restrict__ qin, __half* __restrict__ qout,
         const int* __restrict__ deg, const int* __restrict__ col,
         const float* __restrict__ dinv) {
    int tid = blockIdx.x * blockDim.x + threadIdx.x;
    int n = tid >> 5;
    if (n >= N_NODES) return;
    int lane = tid & 31;

    float acc[8];
    row_sum_h(qin, col + (size_t)n * MAXDEG, deg[n], lane, acc);

    if (lane < 8) {
        float d = dinv[n];
        float s = d * d;
        __half2 h0 = __floats2half2_rn(acc[0] * s, acc[1] * s);
        __half2 h1 = __floats2half2_rn(acc[2] * s, acc[3] * s);
        __half2 h2 = __floats2half2_rn(acc[4] * s, acc[5] * s);
        __half2 h3 = __floats2half2_rn(acc[6] * s, acc[7] * s);
        uint4 o;
        o.x = *(unsigned*)&h0; o.y = *(unsigned*)&h1;
        o.z = *(unsigned*)&h2; o.w = *(unsigned*)&h3;
        *((uint4*)(qout + (size_t)n * EMB) + lane) = o;
    }
}

// ---------------------------------------------------------------------------
// Fused layer-3 + epilogue. One warp per (role, batch-row), n = node id:
//   rep3 = dinv[n] * sum q2[s]
//   final = 0.25 * ( emb[n] + sq*(q1[n]+q2[n]) + rep3 ),  sq = 1/dinv[n]
__global__ void __launch_bounds__(256)
k_final(float* __restrict__ out,
        const float* __restrict__ emb,
        const __half* __restrict__ q1,
        const __half* __restrict__ q2,
        const int* __restrict__ deg, const int* __restrict__ col,
        const float* __restrict__ dinv,
        const int* __restrict__ users, const int* __restrict__ pos,
        const int* __restrict__ neg) {
    int tid = blockIdx.x * blockDim.x + threadIdx.x;
    int w = tid >> 5;
    if (w >= 3 * BATCH) return;
    int lane = tid & 31;

    int role = w / BATCH;
    int b = w - role * BATCH;
    int n = (role == 0) ? users[b]
          : (role == 1) ? (N_USERS + pos[b])
                        : (N_USERS + neg[b]);

    float acc[8];
    row_sum_h(q2, col + (size_t)n * MAXDEG, deg[n], lane, acc);

    if (lane < 8) {
        float d = dinv[n];
        float sq = __fdividef(1.0f, d);   // sqrt(deg), or 1 when deg==0
        size_t ro = (size_t)n * EMB + lane * 8;

        float4 e0 = *(const float4*)(emb + ro);
        float4 e1 = *(const float4*)(emb + ro + 4);
        uint4 a1 = *((const uint4*)(q1 + (size_t)n * EMB) + lane);
        uint4 a2 = *((const uint4*)(q2 + (size_t)n * EMB) + lane);
        const __half2* h1 = (const __half2*)&a1;
        const __half2* h2 = (const __half2*)&a2;

        float r[8];
        #pragma unroll
        for (int k = 0; k < 4; ++k) {
            float2 f1 = __half22float2(h1[k]);
            float2 f2 = __half22float2(h2[k]);
            r[2*k]   = sq * (f1.x + f2.x) + d * acc[2*k];
            r[2*k+1] = sq * (f1.y + f2.y) + d * acc[2*k+1];
        }
        float4 o0, o1;
        o0.x = (e0.x + r[0]) * 0.25f; o0.y = (e0.y + r[1]) * 0.25f;
        o0.z = (e0.z + r[2]) * 0.25f; o0.w = (e0.w + r[3]) * 0.25f;
        o1.x = (e1.x + r[4]) * 0.25f; o1.y = (e1.y + r[5]) * 0.25f;
        o1.z = (e1.z + r[6]) * 0.25f; o1.w = (e1.w + r[7]) * 0.25f;

        size_t wo = (size_t)(role * BATCH + b) * EMB + lane * 8;
        *(float4*)(out + wo)     = o0;
        *(float4*)(out + wo + 4) = o1;
    }

    if (role == 0) {
        int p = N_USERS + pos[b];
        int g = N_USERS + neg[b];
        int c = lane * 2;
        float2 eu = *(const float2*)(emb + (size_t)n * EMB + c);
        float2 ep = *(const float2*)(emb + (size_t)p * EMB + c);
        float2 eg = *(const float2*)(emb + (size_t)g * EMB + c);
        float sum = eu.x * eu.x + eu.y * eu.y
                  + ep.x * ep.x + ep.y * ep.y
                  + eg.x * eg.x + eg.y * eg.y;
        #pragma unroll
        for (int off = 16; off > 0; off >>= 1)
            sum += __shfl_xor_sync(0xFFFFFFFFu, sum, off);
        if (lane == 0)
            out[(size_t)3 * BATCH * EMB + b] = sum;
    }
}

// ---------------------------------------------------------------------------
extern "C" void kernel_launch(void* const* d_in, const int* in_sizes, int n_in,
                              void* d_out, int out_size) {
    const float* emb   = (const float*)d_in[0];
    const int*   eu    = (const int*)  d_in[1];
    const int*   ei    = (const int*)  d_in[2];
    const int*   users = (const int*)  d_in[3];
    const int*   pos   = (const int*)  d_in[4];
    const int*   neg   = (const int*)  d_in[5];
    float* out = (float*)d_out;
    const int E = in_sizes[1];

    __half *q0, *q1, *q2;
    float *dinv;
    int *deg, *cursor, *col;
    cudaGetSymbolAddress((void**)&q0,     g_q0);
    cudaGetSymbolAddress((void**)&q1,     g_q1);
    cudaGetSymbolAddress((void**)&q2,     g_q2);
    cudaGetSymbolAddress((void**)&dinv,   g_dinv);
    cudaGetSymbolAddress((void**)&deg,    g_deg);
    cudaGetSymbolAddress((void**)&cursor, g_cursor);
    cudaGetSymbolAddress((void**)&col,    g_col);

    const int TB = 256;

    // ---- padded-CSR build (cursor zeroed at load / by previous replay's k_dq) ----
    k_fill<<<(E / 2 + TB - 1) / TB, TB>>>(eu, ei, cursor, col, E);
    k_dq<<<(N_NODES * 32 + TB - 1) / TB, TB>>>(cursor, deg, dinv,
                                               (const float4*)emb, (uint2*)q0);

    // ---- layers 1 & 2 ----
    const int pullBlocks = (N_NODES * 32 + TB - 1) / TB;
    k_pull_h<<<pullBlocks, TB>>>(q0, q1, deg, col, dinv);
    k_pull_h<<<pullBlocks, TB>>>(q1, q2, deg, col, dinv);

    // ---- fused layer 3 + epilogue ----
    const int finalBlocks = (3 * BATCH * 32 + TB - 1) / TB;
    k_final<<<finalBlocks, TB>>>(out, emb, q1, q2, deg, col, dinv,
                                 users, pos, neg);
}